// round 16
// baseline (speedup 1.0000x reference)
#include <cuda_runtime.h>
#include <cuda_bf16.h>

#define TT 512
#define MM 16
#define MQ 4
#define PP 600
#define BB 32
#define PW 32
#define NPT 19
#define NTILE (BB * NPT)      // 608 (b,tile) pairs
#define KCAP 512

typedef unsigned long long ull;

// ---- device scratch (static; no allocations) ----
__device__ __align__(16) int    g_K[NTILE];
__device__ __align__(16) float  g_x [NTILE][KCAP + 2];          // scaled compacted x
__device__ __align__(16) float2 g_ky[NTILE][MM][KCAP + 2];      // (mask,y) compacted

__device__ __forceinline__ float ex2(float v) {
    float r;
    asm("ex2.approx.ftz.f32 %0, %1;" : "=f"(r) : "f"(v));
    return r;
}
__device__ __forceinline__ ull pack2(float lo, float hi) {
    ull r;
    asm("mov.b64 %0, {%1, %2};" : "=l"(r) : "f"(lo), "f"(hi));
    return r;
}
__device__ __forceinline__ void unpack2(ull v, float& lo, float& hi) {
    asm("mov.b64 {%0, %1}, %2;" : "=f"(lo), "=f"(hi) : "l"(v));
}
__device__ __forceinline__ ull fma2(ull a, ull b, ull c) {
    ull d;
    asm("fma.rn.f32x2 %0, %1, %2, %3;" : "=l"(d) : "l"(a), "l"(b), "l"(c));
    return d;
}

// ================= kernel 1: compaction + gather into scratch =================
// grid (NPT, BB, 4), block 32. Each warp handles (b, tile, 4-m group).
__global__ __launch_bounds__(32) void prep_kernel(
    const float* __restrict__ y, const float* __restrict__ x,
    const int* __restrict__ mask, const float* __restrict__ sigma)
{
    __shared__ int sidx[KCAP];
    const int lane = threadIdx.x;
    const int tile = blockIdx.x;
    const int b    = blockIdx.y;
    const int q    = blockIdx.z;
    const int tid  = b * NPT + tile;

    const float s0 = sigma[0], s1 = sigma[1];
    const float LOG2E = 1.4426950408889634f;
    const float smax  = fmaxf(s0, s1);
    const float rcmin = sqrtf(0.5f * LOG2E) / smax;

    const int   pfirst = tile * PW;
    const float gA = fmaf((float)pfirst,            50.0f / 599.0f, -1.0f);
    const float gZ = fmaf((float)(pfirst + PW - 1), 50.0f / 599.0f, -1.0f);
    const float vlo = rcmin * gA - 6.7f;    // dropped weight <= 2^-44.9
    const float vhi = rcmin * gZ + 6.7f;

    const float* xr = x + (size_t)b * TT;
    const unsigned lmlt = (1u << lane) - 1u;

    int base = 0;
    #pragma unroll
    for (int r = 0; r < TT / 32; r++) {
        float xs = xr[r * 32 + lane] * rcmin;
        bool in = (xs >= vlo) & (xs <= vhi);
        unsigned msk = __ballot_sync(0xFFFFFFFFu, in);
        if (in) {
            int pos = base + __popc(msk & lmlt);
            sidx[pos] = r * 32 + lane;
            if (q == 0) g_x[tid][pos] = xs;
        }
        base += __popc(msk);
    }
    const int K = base;
    __syncwarp();

    if (q == 0 && lane == 0) {
        g_K[tid] = K;
        if (K < KCAP) g_x[tid][K] = 1.0e9f;      // sentinel -> weight 0
    }

    // gather this warp's 4 m rows in compacted order (coalesced stores)
    const int mbase = q * MQ;
    const float* yb = y    + ((size_t)b * MM + mbase) * TT;
    const int*   mb = mask + ((size_t)b * MM + mbase) * TT;
    for (int j = lane; j < K; j += 32) {
        int t = sidx[j];
        #pragma unroll
        for (int mm = 0; mm < MQ; mm++)
            g_ky[tid][mbase + mm][j] =
                make_float2((float)__ldg(mb + mm * TT + t), __ldg(yb + mm * TT + t));
    }
    if (lane == 0 && K < KCAP) {
        #pragma unroll
        for (int mm = 0; mm < MQ; mm++)
            g_ky[tid][mbase + mm][K] = make_float2(0.f, 0.f);   // pad entry
    }
}

// ================= kernel 2: pure streaming accumulate =================
// grid (NPT, BB, 4), block 32. 2432 warps, all resident, no smem, no syncs.
template<bool EQ>
__global__ __launch_bounds__(32) void main_kernel(
    const float* __restrict__ sigma, float* __restrict__ out)
{
    const int lane = threadIdx.x;
    const int tile = blockIdx.x;
    const int b    = blockIdx.y;
    const int q    = blockIdx.z;
    const int tid  = b * NPT + tile;

    const float s0 = sigma[0], s1 = sigma[1];
    const float LOG2E = 1.4426950408889634f;
    const float smax  = fmaxf(s0, s1);
    const float rcmin = sqrtf(0.5f * LOG2E) / smax;
    const float r0 = (smax / s0) * (smax / s0);
    const float r1 = (smax / s1) * (smax / s1);

    const int   p = tile * PW + lane;
    const float v = rcmin * fmaf((float)p, 50.0f / 599.0f, -1.0f);

    const int K  = g_K[tid];
    const int Kp = (K + 1) & ~1;

    ull acc[MQ];
    #pragma unroll
    for (int m = 0; m < MQ; m++) acc[m] = 0ULL;

    const float*  xp  = g_x[tid];
    const float2* ky0 = g_ky[tid][q * MQ + 0];
    const float2* ky1 = g_ky[tid][q * MQ + 1];
    const float2* ky2 = g_ky[tid][q * MQ + 2];
    const float2* ky3 = g_ky[tid][q * MQ + 3];

    #pragma unroll 4
    for (int jj = 0; jj < Kp; jj += 2) {
        float2 xv = __ldg((const float2*)(xp + jj));      // broadcast
        float d0 = v - xv.x, d1 = v - xv.y;
        float e0 = d0 * (-d0), e1 = d1 * (-d1);

        ull wp0, wp1;
        if (EQ) {
            float w0 = ex2(e0), w1 = ex2(e1);
            wp0 = pack2(w0, w0);
            wp1 = pack2(w1, w1);
        } else {
            wp0 = pack2(ex2(e0 * r0), ex2(e0 * r1));
            wp1 = pack2(ex2(e1 * r0), ex2(e1 * r1));
        }

        ulonglong2 q0 = __ldg((const ulonglong2*)(ky0 + jj));  // broadcast 16B
        ulonglong2 q1 = __ldg((const ulonglong2*)(ky1 + jj));
        ulonglong2 q2 = __ldg((const ulonglong2*)(ky2 + jj));
        ulonglong2 q3 = __ldg((const ulonglong2*)(ky3 + jj));
        acc[0] = fma2(q0.y, wp1, fma2(q0.x, wp0, acc[0]));
        acc[1] = fma2(q1.y, wp1, fma2(q1.x, wp0, acc[1]));
        acc[2] = fma2(q2.y, wp1, fma2(q2.x, wp0, acc[2]));
        acc[3] = fma2(q3.y, wp1, fma2(q3.x, wp0, acc[3]));
    }

    if (p < PP) {
        float4* op = (float4*)(out + ((size_t)b * PP + p) * (2 * MM) + q * 2 * MQ);
        #pragma unroll
        for (int m = 0; m < MQ; m += 2) {
            float dA, cA, dB, cB;
            unpack2(acc[m],     dA, cA);
            unpack2(acc[m + 1], dB, cB);
            op[m >> 1] = make_float4(dA, __fdividef(cA, dA + 1e-8f),
                                     dB, __fdividef(cB, dB + 1e-8f));
        }
    }
}

extern "C" void kernel_launch(void* const* d_in, const int* in_sizes, int n_in,
                              void* d_out, int out_size) {
    const float* y     = (const float*)d_in[0];
    const float* x     = (const float*)d_in[1];
    const int*   mask  = (const int*)  d_in[2];
    const float* sigma = (const float*)d_in[3];
    float*       out   = (float*)d_out;

    dim3 grid(NPT, BB, 4);
    prep_kernel<<<grid, 32>>>(y, x, mask, sigma);
    // sigma equality is data-dependent; launch both paths? No — branch must be
    // resolved on device. Use the general kernel only when needed via a single
    // templated kernel that checks at runtime per-warp (cheap, uniform branch):
    main_kernel<false><<<grid, 32>>>(sigma, out);
}

// round 17
// speedup vs baseline: 1.1011x; 1.1011x over previous
#include <cuda_runtime.h>
#include <cuda_bf16.h>

#define TT 512
#define MM 16
#define MQ 4
#define PP 600
#define BB 32
#define PW 32
#define NPT 19
#define NTILE (BB * NPT)        // 608 (b,tile) pairs
#define UNITS (NTILE * 4)       // 2432 warp units for kernel 2
#define WPB2 8
#define NBLK2 ((UNITS + WPB2 - 1) / WPB2)   // 304
#define KCAP 512
#define CH 64                   // stage/mma chunk (typical K ~53 -> one chunk)

typedef unsigned long long ull;

// ---- device scratch (static; no allocations) ----
__device__ __align__(16) int    g_K[NTILE];
__device__ __align__(16) float  g_x [NTILE][KCAP + 4];        // scaled compacted x
__device__ __align__(16) float2 g_ky[NTILE][MM][KCAP + 2];    // (mask,y) compacted

__device__ __forceinline__ float ex2(float v) {
    float r;
    asm("ex2.approx.ftz.f32 %0, %1;" : "=f"(r) : "f"(v));
    return r;
}
__device__ __forceinline__ ull pack2(float lo, float hi) {
    ull r;
    asm("mov.b64 %0, {%1, %2};" : "=l"(r) : "f"(lo), "f"(hi));
    return r;
}
__device__ __forceinline__ void unpack2(ull v, float& lo, float& hi) {
    asm("mov.b64 {%0, %1}, %2;" : "=f"(lo), "=f"(hi) : "l"(v));
}
__device__ __forceinline__ ull fma2(ull a, ull b, ull c) {
    ull d;
    asm("fma.rn.f32x2 %0, %1, %2, %3;" : "=l"(d) : "l"(a), "l"(b), "l"(c));
    return d;
}

// ============ kernel 1: compaction (once per tile) + gather into scratch ======
// grid (NPT, BB), block 128: warp 0 scans; each warp gathers its 4 m rows.
__global__ __launch_bounds__(128) void prep_kernel(
    const float* __restrict__ y, const float* __restrict__ x,
    const int* __restrict__ mask, const float* __restrict__ sigma)
{
    __shared__ int sidx[KCAP];
    __shared__ int sKsh;
    const int lane = threadIdx.x & 31;
    const int w    = threadIdx.x >> 5;
    const int tile = blockIdx.x;
    const int b    = blockIdx.y;
    const int tid  = b * NPT + tile;

    const float s0 = sigma[0], s1 = sigma[1];
    const float LOG2E = 1.4426950408889634f;
    const float smax  = fmaxf(s0, s1);
    const float rcmin = sqrtf(0.5f * LOG2E) / smax;

    const int   pfirst = tile * PW;
    const float gA = fmaf((float)pfirst,            50.0f / 599.0f, -1.0f);
    const float gZ = fmaf((float)(pfirst + PW - 1), 50.0f / 599.0f, -1.0f);
    const float vlo = rcmin * gA - 6.7f;    // dropped weight <= 2^-44.9
    const float vhi = rcmin * gZ + 6.7f;

    if (w == 0) {
        const float* xr = x + (size_t)b * TT;
        const unsigned lmlt = (1u << lane) - 1u;
        int base = 0;
        #pragma unroll
        for (int r = 0; r < TT / 32; r++) {
            float xs = xr[r * 32 + lane] * rcmin;
            bool in = (xs >= vlo) & (xs <= vhi);
            unsigned msk = __ballot_sync(0xFFFFFFFFu, in);
            if (in) {
                int pos = base + __popc(msk & lmlt);
                sidx[pos] = r * 32 + lane;
                g_x[tid][pos] = xs;
            }
            base += __popc(msk);
        }
        if (lane == 0) {
            sKsh = base;
            g_K[tid] = base;
            if (base < KCAP) g_x[tid][base] = 1.0e9f;   // sentinel -> weight 0
        }
    }
    __syncthreads();
    const int K = sKsh;

    const int mbase = w * MQ;
    const float* yb = y    + ((size_t)b * MM + mbase) * TT;
    const int*   mb = mask + ((size_t)b * MM + mbase) * TT;
    for (int j = lane; j < K; j += 32) {
        int t = sidx[j];
        #pragma unroll
        for (int mm = 0; mm < MQ; mm++)
            g_ky[tid][mbase + mm][j] =
                make_float2((float)__ldg(mb + mm * TT + t), __ldg(yb + mm * TT + t));
    }
    if (lane == 0 && K < KCAP) {
        #pragma unroll
        for (int mm = 0; mm < MQ; mm++)
            g_ky[tid][mbase + mm][K] = make_float2(0.f, 0.f);   // pad entry
    }
}

// ============ kernel 2: dense coalesced stage -> smem mma =====================
// block = 8 autonomous warps; unit = (b, tile, m-quarter); no __syncthreads.
#define SLICE (CH + CH * MQ * 2)   // sx[64] + sky[4][64] float2 = 576 floats

template<bool EQ>
__device__ __forceinline__ void chunk_mma(
    const float* sx, const float2* sky, int n,
    float v, float r0, float r1, ull* __restrict__ acc)
{
    for (int jl = 0; jl < n; jl += 2) {
        float2 xv = *(const float2*)(sx + jl);         // LDS.64 broadcast
        float d0 = v - xv.x, d1 = v - xv.y;
        float e0 = d0 * (-d0), e1 = d1 * (-d1);

        ull wp0, wp1;
        if (EQ) {
            float w0 = ex2(e0), w1 = ex2(e1);
            wp0 = pack2(w0, w0);
            wp1 = pack2(w1, w1);
        } else {
            wp0 = pack2(ex2(e0 * r0), ex2(e0 * r1));
            wp1 = pack2(ex2(e1 * r0), ex2(e1 * r1));
        }

        #pragma unroll
        for (int m = 0; m < MQ; m++) {
            ulonglong2 q = *(const ulonglong2*)(sky + m * CH + jl);  // LDS.128
            acc[m] = fma2(q.y, wp1, fma2(q.x, wp0, acc[m]));
        }
    }
}

template<bool EQ>
__global__ __launch_bounds__(WPB2 * 32) void main_kernel(
    const float* __restrict__ sigma, float* __restrict__ out)
{
    __shared__ float sm[WPB2 * SLICE];
    const int lane = threadIdx.x & 31;
    const int w    = threadIdx.x >> 5;

    const int unit = blockIdx.x * WPB2 + w;
    if (unit >= UNITS) return;                 // warp-level exit; no barriers

    const int quarter = unit & 3;
    const int bt      = unit >> 2;
    const int b       = bt / NPT;
    const int tile    = bt % NPT;
    const int tid     = b * NPT + tile;

    float*  sx  = sm + w * SLICE;
    float2* sky = (float2*)(sx + CH);

    const float s0 = sigma[0], s1 = sigma[1];
    const float LOG2E = 1.4426950408889634f;
    const float smax  = fmaxf(s0, s1);
    const float rcmin = sqrtf(0.5f * LOG2E) / smax;
    const float r0 = (smax / s0) * (smax / s0);
    const float r1 = (smax / s1) * (smax / s1);

    const int   p = tile * PW + lane;
    const float v = rcmin * fmaf((float)p, 50.0f / 599.0f, -1.0f);

    const int K  = g_K[tid];
    const int Kp = (K + 1) & ~1;

    ull acc[MQ];
    #pragma unroll
    for (int m = 0; m < MQ; m++) acc[m] = 0ULL;

    const float* gx = g_x[tid];

    for (int c0 = 0; c0 < Kp; c0 += CH) {
        const int n  = min(CH, Kp - c0);       // even
        const int n2 = n >> 1;                 // float4 / float2 pair count

        // dense coalesced stage: sx chunk + 4 ky rows (no gather, no scan)
        if (lane < n2)
            ((float2*)sx)[lane] = ((const float2*)(gx + c0))[lane];
        #pragma unroll
        for (int mm = 0; mm < MQ; mm++) {
            const float4* src = (const float4*)(&g_ky[tid][quarter * MQ + mm][c0]);
            if (lane < n2)
                ((float4*)(sky + mm * CH))[lane] = __ldg(src + lane);
        }
        __syncwarp();

        chunk_mma<EQ>(sx, sky, n, v, r0, r1, acc);
        __syncwarp();
    }

    if (p < PP) {
        float4* op = (float4*)(out + ((size_t)b * PP + p) * (2 * MM)
                               + quarter * 2 * MQ);
        #pragma unroll
        for (int m = 0; m < MQ; m += 2) {
            float dA, cA, dB, cB;
            unpack2(acc[m],     dA, cA);
            unpack2(acc[m + 1], dB, cB);
            op[m >> 1] = make_float4(dA, __fdividef(cA, dA + 1e-8f),
                                     dB, __fdividef(cB, dB + 1e-8f));
        }
    }
}

extern "C" void kernel_launch(void* const* d_in, const int* in_sizes, int n_in,
                              void* d_out, int out_size) {
    const float* y     = (const float*)d_in[0];
    const float* x     = (const float*)d_in[1];
    const int*   mask  = (const int*)  d_in[2];
    const float* sigma = (const float*)d_in[3];
    float*       out   = (float*)d_out;

    dim3 pgrid(NPT, BB);
    prep_kernel<<<pgrid, 128>>>(y, x, mask, sigma);
    main_kernel<false><<<NBLK2, WPB2 * 32>>>(sigma, out);
}